// round 15
// baseline (speedup 1.0000x reference)
#include <cuda_runtime.h>

// residual = K3 * (K2 * (K1 * x)), depthwise, per-stage zero padding.
// Register-rolling column strips, fully unrolled 36-step pipeline, ONE launch.
// K3 is folded into K2's horizontal rank-2 factors:
//   out = A (x) q0 + B (x) q1   applied to edge,
//   A=[1,0,-2,0,1], B=[0,1,-2,1,0],
//   q0 = k3*r0 = [-1,4,-7,8,-7,4,-1], q1 = k3*r1 = [2,-10,22,-28,22,-10,2].
// Folding bypasses tex zero-padding at x=-1/512, which only affects output
// cols 0 and 511: threads 0/127 keep a tex-boundary ring TXm (old H0/Hh at
// the phantom column, simplified by known E zeros) subtracted at finalize.
//  - thread t owns output cols [4t,4t+4); 128 threads = full 512 width
//  - block sweeps a 32-row band; step T: prefetch input row e+2 (dist 1),
//    compute edge row e=Y0-2+T (K1 = S(x)S - 2 D(x)D), G0/Gh per output col,
//    scatter into OA ring (5 slots x 4 cols), store output row Y0-4+T.
//  - OA slot for out row y is FIRST touched as the S4 slot (assignment).
//  - Row-validity checks only at literal boundary steps (ntop/nbot bools).

#define IMG  512
#define BAND 32
#define NTH  128

// Load input row (Y0-3+REL), cols cx-4..cx+7, into DST[12]; ROK: row validity.
#define LOADROW(DST, REL, ROK) do {                                             \
    const float4 _z = make_float4(0.f, 0.f, 0.f, 0.f);                         \
    const bool _rok = (ROK);                                                    \
    const float* _p = ip + (long)(REL) * IMG;                                   \
    float4 _va = (_rok && okL) ? *reinterpret_cast<const float4*>(_p)     : _z; \
    float4 _vb =  _rok         ? *reinterpret_cast<const float4*>(_p + 4) : _z; \
    float4 _vc = (_rok && okR) ? *reinterpret_cast<const float4*>(_p + 8) : _z; \
    DST[0]=_va.x; DST[1]=_va.y; DST[2]=_va.z;  DST[3]=_va.w;                    \
    DST[4]=_vb.x; DST[5]=_vb.y; DST[6]=_vb.z;  DST[7]=_vb.w;                    \
    DST[8]=_vc.x; DST[9]=_vc.y; DST[10]=_vc.z; DST[11]=_vc.w;                   \
} while (0)

// One pipeline step. T literal. OA/TXm slots U,S1..S4 = (T..T+4)%5 literals.
// R slots A,B,C = rows e-1,e,e+1 = (T..T+2)%4; D = (T+3)%4 receives row e+2.
// PR: prefetch-row validity; EV: edge-row validity (uniform bools).
#define STEP(T, U, S1, S2, S3, S4, RA, RB, RC, RD, PR, EV) do {                 \
    if ((T) <= 34) LOADROW(R[RD], (T) + 3, PR);   /* prefetch row e+2 */        \
    if (EV) {                                                                   \
        float E[10];                                                            \
        {   /* cols 0..6 -> E[0..4] */                                          \
            float SY[7], DY[7];                                                 \
            _Pragma("unroll")                                                   \
            for (int c = 0; c < 7; c++) {                                       \
                float tb = fmaf(1.f, R[RA][c], R[RC][c]);                       \
                DY[c] = tb; SY[c] = fmaf(2.f, R[RB][c], tb);                    \
            }                                                                   \
            _Pragma("unroll")                                                   \
            for (int j = 0; j < 5; j++) {                                       \
                float sv = fmaf(2.f, SY[j+1], fmaf(1.f, SY[j], SY[j+2]));       \
                E[j] = fmaf(-2.f, fmaf(1.f, DY[j], DY[j+2]), sv);               \
            }                                                                   \
        }                                                                       \
        {   /* cols 5..11 -> E[5..9] */                                         \
            float SY[7], DY[7];                                                 \
            _Pragma("unroll")                                                   \
            for (int c = 0; c < 7; c++) {                                       \
                float tb = fmaf(1.f, R[RA][c+5], R[RC][c+5]);                   \
                DY[c] = tb; SY[c] = fmaf(2.f, R[RB][c+5], tb);                  \
            }                                                                   \
            _Pragma("unroll")                                                   \
            for (int j = 0; j < 5; j++) {                                       \
                float sv = fmaf(2.f, SY[j+1], fmaf(1.f, SY[j], SY[j+2]));       \
                E[j+5] = fmaf(-2.f, fmaf(1.f, DY[j], DY[j+2]), sv);             \
            }                                                                   \
        }                                                                       \
        if (tid == 0) {                                                         \
            E[0] = 0.f; E[1] = 0.f; E[2] = 0.f;   /* edge zero-pad, left */     \
            /* phantom tex col -1: H0m/Hhm with E[0..2]=0 */                    \
            float H0m = fmaf(2.f, E[3], -E[4]);                                 \
            float Hhm = fmaf(-3.f, E[3], E[4]);                                 \
            TXm[U]  = fmaf(1.f, H0m, TXm[U]);                                   \
            TXm[S1] = fmaf(2.f, Hhm, TXm[S1]);                                  \
            TXm[S2] = fmaf(-2.f, H0m, fmaf(-4.f, Hhm, TXm[S2]));                \
            TXm[S3] = fmaf(2.f, Hhm, TXm[S3]);                                  \
            TXm[S4] = H0m;                                                      \
        } else if (tid == NTH-1) {                                              \
            E[7] = 0.f; E[8] = 0.f; E[9] = 0.f;   /* edge zero-pad, right */    \
            /* phantom tex col 512: with E[7..9]=0 */                           \
            float H0m = fmaf(2.f, E[6], -E[5]);                                 \
            float Hhm = fmaf(-3.f, E[6], E[5]);                                 \
            TXm[U]  = fmaf(1.f, H0m, TXm[U]);                                   \
            TXm[S1] = fmaf(2.f, Hhm, TXm[S1]);                                  \
            TXm[S2] = fmaf(-2.f, H0m, fmaf(-4.f, Hhm, TXm[S2]));                \
            TXm[S3] = fmaf(2.f, Hhm, TXm[S3]);                                  \
            TXm[S4] = H0m;                                                      \
        }                                                                       \
        _Pragma("unroll")                                                       \
        for (int c = 0; c < 4; c++) {                                           \
            float p1 = fmaf(1.f, E[c],   E[c+6]);                               \
            float p2 = fmaf(1.f, E[c+1], E[c+5]);                               \
            float p3 = fmaf(1.f, E[c+2], E[c+4]);                               \
            float t0 = fmaf(4.f, p2, -p1);                                      \
            t0 = fmaf(-7.f, p3, t0);                                            \
            float G0 = fmaf(8.f, E[c+3], t0);                                   \
            float u0 = fmaf(-5.f, p2, p1);                                      \
            u0 = fmaf(11.f, p3, u0);                                            \
            float Gh = fmaf(-14.f, E[c+3], u0);        /* = G1/2 */             \
            OA[U][c]  = fmaf( 1.f, G0, OA[U][c]);              /* y=e-2 */      \
            OA[S1][c] = fmaf( 2.f, Gh, OA[S1][c]);             /* y=e-1 */      \
            OA[S2][c] = fmaf(-2.f, G0, fmaf(-4.f, Gh, OA[S2][c])); /* y=e */    \
            OA[S3][c] = fmaf( 2.f, Gh, OA[S3][c]);             /* y=e+1 */      \
            OA[S4][c] = G0;            /* first touch of row y=e+2: assign */   \
        }                                                                       \
    } else {                                                                    \
        _Pragma("unroll")                                                       \
        for (int c = 0; c < 4; c++) OA[S4][c] = 0.f;  /* edge row is zero */    \
        TXm[S4] = 0.f;                                                          \
    }                                                                           \
    if ((T) >= 4) {   /* store output row y = Y0-4+T from slot U */             \
        float4 o;                                                               \
        o.x = OA[U][0]; o.y = OA[U][1]; o.z = OA[U][2]; o.w = OA[U][3];         \
        if (tid == 0)          o.x -= TXm[U];                                   \
        else if (tid == NTH-1) o.w -= TXm[U];                                   \
        *reinterpret_cast<float4*>(op + (long)((T) - 4) * IMG) = o;             \
    }                                                                           \
} while (0)

__global__ __launch_bounds__(NTH, 5)
void rf_kernel(const float* __restrict__ x, float* __restrict__ out)
{
    const int tid = threadIdx.x;
    const int Y0  = (int)blockIdx.x * BAND;
    const long base = (long)blockIdx.y * (IMG * IMG);
    const int cx  = tid * 4;
    const bool okL = (tid != 0);
    const bool okR = (tid != NTH - 1);
    const bool ntop = (Y0 != 0);               // rows above band exist
    const bool nbot = (Y0 != IMG - BAND);      // rows below band exist

    float R[4][12];    // input-row ring: slot(rel r) = r % 4, rel = row-(Y0-3)
    float OA[5][4];    // output accumulator ring: 5 live rows, 4 cols
    float TXm[5];      // phantom tex-column ring (threads 0/127 only)

    const float* ip = x + base + (long)(Y0 - 3) * IMG + (cx - 4);
    float* op = out + base + (long)Y0 * IMG + cx;

    // prime rows Y0-3, Y0-2, Y0-1 -> slots 0,1,2 (step 0 prefetches Y0 -> 3)
    LOADROW(R[0], 0, ntop);
    LOADROW(R[1], 1, ntop);
    LOADROW(R[2], 2, ntop);

    STEP( 0, 0,1,2,3,4, 0,1,2,3, true, ntop);
    STEP( 1, 1,2,3,4,0, 1,2,3,0, true, ntop);
    STEP( 2, 2,3,4,0,1, 2,3,0,1, true, true);
    STEP( 3, 3,4,0,1,2, 3,0,1,2, true, true);
    STEP( 4, 4,0,1,2,3, 0,1,2,3, true, true);
    STEP( 5, 0,1,2,3,4, 1,2,3,0, true, true);
    STEP( 6, 1,2,3,4,0, 2,3,0,1, true, true);
    STEP( 7, 2,3,4,0,1, 3,0,1,2, true, true);
    STEP( 8, 3,4,0,1,2, 0,1,2,3, true, true);
    STEP( 9, 4,0,1,2,3, 1,2,3,0, true, true);
    STEP(10, 0,1,2,3,4, 2,3,0,1, true, true);
    STEP(11, 1,2,3,4,0, 3,0,1,2, true, true);
    STEP(12, 2,3,4,0,1, 0,1,2,3, true, true);
    STEP(13, 3,4,0,1,2, 1,2,3,0, true, true);
    STEP(14, 4,0,1,2,3, 2,3,0,1, true, true);
    STEP(15, 0,1,2,3,4, 3,0,1,2, true, true);
    STEP(16, 1,2,3,4,0, 0,1,2,3, true, true);
    STEP(17, 2,3,4,0,1, 1,2,3,0, true, true);
    STEP(18, 3,4,0,1,2, 2,3,0,1, true, true);
    STEP(19, 4,0,1,2,3, 3,0,1,2, true, true);
    STEP(20, 0,1,2,3,4, 0,1,2,3, true, true);
    STEP(21, 1,2,3,4,0, 1,2,3,0, true, true);
    STEP(22, 2,3,4,0,1, 2,3,0,1, true, true);
    STEP(23, 3,4,0,1,2, 3,0,1,2, true, true);
    STEP(24, 4,0,1,2,3, 0,1,2,3, true, true);
    STEP(25, 0,1,2,3,4, 1,2,3,0, true, true);
    STEP(26, 1,2,3,4,0, 2,3,0,1, true, true);
    STEP(27, 2,3,4,0,1, 3,0,1,2, true, true);
    STEP(28, 3,4,0,1,2, 0,1,2,3, true, true);
    STEP(29, 4,0,1,2,3, 1,2,3,0, true, true);
    STEP(30, 0,1,2,3,4, 2,3,0,1, true, true);
    STEP(31, 1,2,3,4,0, 3,0,1,2, true, true);
    STEP(32, 2,3,4,0,1, 0,1,2,3, nbot, true);
    STEP(33, 3,4,0,1,2, 1,2,3,0, nbot, true);
    STEP(34, 4,0,1,2,3, 2,3,0,1, nbot, nbot);
    STEP(35, 0,1,2,3,4, 3,0,1,2, true, nbot);
}

extern "C" void kernel_launch(void* const* d_in, const int* in_sizes, int n_in,
                              void* d_out, int out_size)
{
    const float* x = (const float*)d_in[0];
    float* out = (float*)d_out;
    const int planes = in_sizes[0] / (IMG * IMG);   // 64*3 = 192

    dim3 grid(IMG / BAND, planes);                  // (16, 192) = 3072 blocks
    rf_kernel<<<grid, NTH>>>(x, out);
}

// round 16
// speedup vs baseline: 1.0547x; 1.0547x over previous
#include <cuda_runtime.h>

// residual = K3 * (K2 * (K1 * x)), depthwise, per-stage zero padding.
// R14 structure (register-rolling column strips, 36-step unrolled pipeline,
// one launch) with all column math vectorized via packed f32x2 (SASS FFMA2):
//  - thread t owns output cols [4t,4t+4); columns packed in pairs into 64-bit
//    registers (low word = lower column index).
//  - K1 = S(x)S - 2 D(x)D   (S=[1,2,1], D=[1,0,1])  -> edge row E[0..9]
//  - K2 = A(x)r0 + B(x)r1   (A=[1,0,-2,0,1], B=[0,1,-2,1,0],
//         r0=[-1,2,-2,2,-1], r1=[2,-6,8,-6,2]) -> H0/Hh per tex col, vertical
//         scatter into TA ring (5 rows x 3 col-pairs)
//  - K3 = [1,-2,1] horizontal at finalize (packed; x-edge fix by scalar
//         subtraction on the boundary half-word, threads 0/127 only)
//  - Odd-alignment column pairs built with mov.b64 repacks (alu pipe).
//  - Row-validity checks only at literal boundary steps (ntop/nbot bools).

#define IMG  512
#define BAND 32
#define NTH  128

typedef unsigned long long u64;

#define F2FMA(d,a,b,c) asm("fma.rn.f32x2 %0, %1, %2, %3;" : "=l"(d) : "l"(a), "l"(b), "l"(c))
#define F2ADD(d,a,b)   asm("add.rn.f32x2 %0, %1, %2;"     : "=l"(d) : "l"(a), "l"(b))
#define F2MUL(d,a,b)   asm("mul.rn.f32x2 %0, %1, %2;"     : "=l"(d) : "l"(a), "l"(b))
// d = (hi(p), lo(q)) : the odd-aligned pair between packed p and q
#define PACKODD(d,p,q) asm("{\n\t.reg .b32 _l0,_h0,_l1,_h1;\n\t" \
                           "mov.b64 {_l0,_h0}, %1;\n\t" \
                           "mov.b64 {_l1,_h1}, %2;\n\t" \
                           "mov.b64 %0, {_h0,_l1};\n\t}" \
                           : "=l"(d) : "l"(p), "l"(q))

// Load input row (Y0-3+REL), cols cx-4..cx+7, as 6 packed pairs; ROK validity.
#define LOADROW(DST, REL, ROK) do {                                             \
    const ulonglong2 _z = make_ulonglong2(0ULL, 0ULL);                          \
    const bool _rok = (ROK);                                                    \
    const float* _p = ip + (long)(REL) * IMG;                                   \
    ulonglong2 _va = (_rok && okL) ? *reinterpret_cast<const ulonglong2*>(_p)     : _z; \
    ulonglong2 _vb =  _rok         ? *reinterpret_cast<const ulonglong2*>(_p + 4) : _z; \
    ulonglong2 _vc = (_rok && okR) ? *reinterpret_cast<const ulonglong2*>(_p + 8) : _z; \
    DST[0]=_va.x; DST[1]=_va.y; DST[2]=_vb.x;                                   \
    DST[3]=_vb.y; DST[4]=_vc.x; DST[5]=_vc.y;                                   \
} while (0)

// One pipeline step. T literal. TA slots U,S1..S4 = (T..T+4)%5 literals.
// R slots RA,RB,RC = rows e-1,e,e+1 = (T..T+2)%4; RD = (T+3)%4 gets row e+2.
// PR: prefetch-row validity; EV: edge-row validity (uniform bools).
#define STEP(T, U, S1, S2, S3, S4, RA, RB, RC, RD, PR, EV) do {                 \
    if ((T) <= 34) LOADROW(R[RD], (T) + 3, PR);   /* prefetch row e+2 */        \
    if (EV) {                                                                   \
        u64 SYp[6], DYp[6], Ep[5];                                              \
        _Pragma("unroll")                                                       \
        for (int k = 0; k < 6; k++) {          /* DY = top+bot, SY = DY+2mid */ \
            F2ADD(DYp[k], R[RA][k], R[RC][k]);                                  \
            F2FMA(SYp[k], C2, R[RB][k], DYp[k]);                                \
        }                                                                       \
        _Pragma("unroll")                                                       \
        for (int m = 0; m < 5; m++) {   /* E = SY*[1,2,1] - 2*DY*[1,0,1] */     \
            u64 syb, t1, t2, t3;                                                \
            PACKODD(syb, SYp[m], SYp[m+1]);                                     \
            F2ADD(t1, SYp[m], SYp[m+1]);                                        \
            F2FMA(t2, C2, syb, t1);                                             \
            F2ADD(t3, DYp[m], DYp[m+1]);                                        \
            F2FMA(Ep[m], Cm2, t3, t2);                                          \
        }                                                                       \
        if (tid == 0)          { Ep[0] = 0ULL; Ep[1] &= 0xFFFFFFFF00000000ULL; }\
        else if (tid == NTH-1) { Ep[3] &= 0x00000000FFFFFFFFULL; Ep[4] = 0ULL; }\
        _Pragma("unroll")                                                       \
        for (int k = 0; k < 3; k++) {     /* tex col pair (2k,2k+1) */          \
            u64 s2a, s2b, s1p, s2p, e2, t, H0, u, Hh, inr;                      \
            PACKODD(s2a, Ep[k],   Ep[k+1]);                                     \
            PACKODD(s2b, Ep[k+1], Ep[k+2]);                                     \
            F2ADD(s1p, Ep[k], Ep[k+2]);                                         \
            F2ADD(s2p, s2a, s2b);                                               \
            F2MUL(e2, Cm2, Ep[k+1]);          /* -2*E[c+2]            */        \
            F2FMA(t,  C2,  s2p, e2);          /* 2s2 - 2Ec2           */        \
            F2FMA(H0, Cm1, s1p, t);           /* -s1 + 2s2 - 2Ec2     */        \
            F2FMA(u,  Cm3, s2p, s1p);         /* s1 - 3s2             */        \
            F2FMA(Hh, C4,  Ep[k+1], u);       /* Hh = H1/2            */        \
            F2ADD(TA[U][k],  H0, TA[U][k]);              /* y=e-2 */            \
            F2FMA(TA[S1][k], C2, Hh, TA[S1][k]);         /* y=e-1 */            \
            F2FMA(inr, C2, Hh, H0);                                             \
            F2FMA(TA[S2][k], Cm2, inr, TA[S2][k]);       /* y=e: -2H0-4Hh */    \
            F2FMA(TA[S3][k], C2, Hh, TA[S3][k]);         /* y=e+1 */            \
            TA[S4][k] = H0;        /* first touch of row y=e+2: assign */       \
        }                                                                       \
    } else {                                                                    \
        TA[S4][0] = 0ULL; TA[S4][1] = 0ULL; TA[S4][2] = 0ULL;                   \
    }                                                                           \
    if ((T) >= 4) {   /* K3 finalize + store output row y = Y0-4+T, slot U */   \
        u64 m01, m23, a0, a1, o01, o23;                                         \
        PACKODD(m01, TA[U][0], TA[U][1]);     /* (t1,t2) */                     \
        PACKODD(m23, TA[U][1], TA[U][2]);     /* (t3,t4) */                     \
        F2ADD(a0, TA[U][0], TA[U][1]);        /* (t0+t2, t1+t3) */              \
        F2ADD(a1, TA[U][1], TA[U][2]);        /* (t2+t4, t3+t5) */              \
        F2FMA(o01, Cm2, m01, a0);                                               \
        F2FMA(o23, Cm2, m23, a1);                                               \
        if (tid == 0) {            /* tex col cx-1 is zero-padded */            \
            float t0f = __uint_as_float((unsigned)TA[U][0]);                    \
            float o0f = __uint_as_float((unsigned)o01) - t0f;                   \
            o01 = (o01 & 0xFFFFFFFF00000000ULL) | (u64)__float_as_uint(o0f);    \
        } else if (tid == NTH-1) { /* tex col cx+4 is zero-padded */            \
            float t5f = __uint_as_float((unsigned)(TA[U][2] >> 32));            \
            float o3f = __uint_as_float((unsigned)(o23 >> 32)) - t5f;           \
            o23 = (o23 & 0x00000000FFFFFFFFULL)                                 \
                | ((u64)__float_as_uint(o3f) << 32);                            \
        }                                                                       \
        ulonglong2 _st; _st.x = o01; _st.y = o23;                               \
        *reinterpret_cast<ulonglong2*>(op + (long)((T) - 4) * IMG) = _st;       \
    }                                                                           \
} while (0)

__global__ __launch_bounds__(NTH, 5)
void rf_kernel(const float* __restrict__ x, float* __restrict__ out)
{
    const int tid = threadIdx.x;
    const int Y0  = (int)blockIdx.x * BAND;
    const long base = (long)blockIdx.y * (IMG * IMG);
    const int cx  = tid * 4;
    const bool okL = (tid != 0);
    const bool okR = (tid != NTH - 1);
    const bool ntop = (Y0 != 0);               // rows above band exist
    const bool nbot = (Y0 != IMG - BAND);      // rows below band exist

    // packed f32x2 constants (both halves identical)
    const u64 C2  = 0x4000000040000000ULL;     //  2.0f
    const u64 Cm2 = 0xC0000000C0000000ULL;     // -2.0f
    const u64 Cm1 = 0xBF800000BF800000ULL;     // -1.0f
    const u64 Cm3 = 0xC0400000C0400000ULL;     // -3.0f
    const u64 C4  = 0x4080000040800000ULL;     //  4.0f

    u64 R[4][6];    // input-row ring: 6 col pairs (cx-4..cx+7); slot = rel%4
    u64 TA[5][3];   // tex accumulator ring: 5 rows x 3 col pairs (cx-1..cx+4)

    const float* ip = x + base + (long)(Y0 - 3) * IMG + (cx - 4);
    float* op = out + base + (long)Y0 * IMG + cx;

    // prime rows Y0-3, Y0-2, Y0-1 -> slots 0,1,2 (step 0 prefetches Y0 -> 3)
    LOADROW(R[0], 0, ntop);
    LOADROW(R[1], 1, ntop);
    LOADROW(R[2], 2, ntop);

    STEP( 0, 0,1,2,3,4, 0,1,2,3, true, ntop);
    STEP( 1, 1,2,3,4,0, 1,2,3,0, true, ntop);
    STEP( 2, 2,3,4,0,1, 2,3,0,1, true, true);
    STEP( 3, 3,4,0,1,2, 3,0,1,2, true, true);
    STEP( 4, 4,0,1,2,3, 0,1,2,3, true, true);
    STEP( 5, 0,1,2,3,4, 1,2,3,0, true, true);
    STEP( 6, 1,2,3,4,0, 2,3,0,1, true, true);
    STEP( 7, 2,3,4,0,1, 3,0,1,2, true, true);
    STEP( 8, 3,4,0,1,2, 0,1,2,3, true, true);
    STEP( 9, 4,0,1,2,3, 1,2,3,0, true, true);
    STEP(10, 0,1,2,3,4, 2,3,0,1, true, true);
    STEP(11, 1,2,3,4,0, 3,0,1,2, true, true);
    STEP(12, 2,3,4,0,1, 0,1,2,3, true, true);
    STEP(13, 3,4,0,1,2, 1,2,3,0, true, true);
    STEP(14, 4,0,1,2,3, 2,3,0,1, true, true);
    STEP(15, 0,1,2,3,4, 3,0,1,2, true, true);
    STEP(16, 1,2,3,4,0, 0,1,2,3, true, true);
    STEP(17, 2,3,4,0,1, 1,2,3,0, true, true);
    STEP(18, 3,4,0,1,2, 2,3,0,1, true, true);
    STEP(19, 4,0,1,2,3, 3,0,1,2, true, true);
    STEP(20, 0,1,2,3,4, 0,1,2,3, true, true);
    STEP(21, 1,2,3,4,0, 1,2,3,0, true, true);
    STEP(22, 2,3,4,0,1, 2,3,0,1, true, true);
    STEP(23, 3,4,0,1,2, 3,0,1,2, true, true);
    STEP(24, 4,0,1,2,3, 0,1,2,3, true, true);
    STEP(25, 0,1,2,3,4, 1,2,3,0, true, true);
    STEP(26, 1,2,3,4,0, 2,3,0,1, true, true);
    STEP(27, 2,3,4,0,1, 3,0,1,2, true, true);
    STEP(28, 3,4,0,1,2, 0,1,2,3, true, true);
    STEP(29, 4,0,1,2,3, 1,2,3,0, true, true);
    STEP(30, 0,1,2,3,4, 2,3,0,1, true, true);
    STEP(31, 1,2,3,4,0, 3,0,1,2, true, true);
    STEP(32, 2,3,4,0,1, 0,1,2,3, nbot, true);
    STEP(33, 3,4,0,1,2, 1,2,3,0, nbot, true);
    STEP(34, 4,0,1,2,3, 2,3,0,1, nbot, nbot);
    STEP(35, 0,1,2,3,4, 3,0,1,2, true, nbot);
}

extern "C" void kernel_launch(void* const* d_in, const int* in_sizes, int n_in,
                              void* d_out, int out_size)
{
    const float* x = (const float*)d_in[0];
    float* out = (float*)d_out;
    const int planes = in_sizes[0] / (IMG * IMG);   // 64*3 = 192

    dim3 grid(IMG / BAND, planes);                  // (16, 192) = 3072 blocks
    rf_kernel<<<grid, NTH>>>(x, out);
}